// round 7
// baseline (speedup 1.0000x reference)
#include <cuda_runtime.h>
#include <math.h>
#include <limits.h>

#define LROW 2048
#define SDIM 65
#define OUT_PER_ROW (SDIM * SDIM)   // 4225
#define THRESH 0.2f
#define EPSV 1e-6f
#define NTHREADS 256

__global__ __launch_bounds__(NTHREADS, 8)
void rp_kernel(const float* __restrict__ x, float* __restrict__ out) {
    const int row = blockIdx.x;
    const int t = threadIdx.x;
    const float4* __restrict__ xr =
        reinterpret_cast<const float4*>(x + (size_t)row * LROW);

    // ---- one-pass row stats: sum, sumsq, min/max nonzero index ----
    const float4 v0 = __ldcs(&xr[t]);            // idx 4t..4t+3 (t<17 holds first 68)
    const float4 v1 = __ldcs(&xr[t + NTHREADS]);

    float sum = 0.f, sumsq = 0.f;
    int mn = INT_MAX, mx = -1;
    {
        const float4 v = v0; const int base = t * 4;
        sum   += (v.x + v.y) + (v.z + v.w);
        sumsq += (v.x * v.x + v.y * v.y) + (v.z * v.z + v.w * v.w);
        if (v.x != 0.f) { mn = min(mn, base + 0); mx = max(mx, base + 0); }
        if (v.y != 0.f) { mn = min(mn, base + 1); mx = max(mx, base + 1); }
        if (v.z != 0.f) { mn = min(mn, base + 2); mx = max(mx, base + 2); }
        if (v.w != 0.f) { mn = min(mn, base + 3); mx = max(mx, base + 3); }
    }
    {
        const float4 v = v1; const int base = (t + NTHREADS) * 4;
        sum   += (v.x + v.y) + (v.z + v.w);
        sumsq += (v.x * v.x + v.y * v.y) + (v.z * v.z + v.w * v.w);
        if (v.x != 0.f) { mn = min(mn, base + 0); mx = max(mx, base + 0); }
        if (v.y != 0.f) { mn = min(mn, base + 1); mx = max(mx, base + 1); }
        if (v.z != 0.f) { mn = min(mn, base + 2); mx = max(mx, base + 2); }
        if (v.w != 0.f) { mn = min(mn, base + 3); mx = max(mx, base + 3); }
    }

    // ---- warp reduce ----
    #pragma unroll
    for (int o = 16; o > 0; o >>= 1) {
        sum   += __shfl_down_sync(0xffffffffu, sum, o);
        sumsq += __shfl_down_sync(0xffffffffu, sumsq, o);
        mn = min(mn, __shfl_down_sync(0xffffffffu, mn, o));
        mx = max(mx, __shfl_down_sync(0xffffffffu, mx, o));
    }

    __shared__ float s_sum[8], s_sq[8];
    __shared__ int   s_mn[8],  s_mx[8];
    const int wid = t >> 5, lid = t & 31;
    if (lid == 0) { s_sum[wid] = sum; s_sq[wid] = sumsq; s_mn[wid] = mn; s_mx[wid] = mx; }
    __syncthreads();

    __shared__ float s_mean, s_rstd;
    __shared__ int   s_start, s_end;
    if (t < 32) {
        sum   = (t < 8) ? s_sum[t] : 0.f;
        sumsq = (t < 8) ? s_sq[t]  : 0.f;
        mn    = (t < 8) ? s_mn[t]  : INT_MAX;
        mx    = (t < 8) ? s_mx[t]  : -1;
        #pragma unroll
        for (int o = 4; o > 0; o >>= 1) {
            sum   += __shfl_down_sync(0xffffffffu, sum, o);
            sumsq += __shfl_down_sync(0xffffffffu, sumsq, o);
            mn = min(mn, __shfl_down_sync(0xffffffffu, mn, o));
            mx = max(mx, __shfl_down_sync(0xffffffffu, mx, o));
        }
        if (t == 0) {
            const float cnt  = (mx >= 0) ? (float)(mx - mn + 1) : 1.f;
            const float mean = sum / cnt;
            const float var  = fmaxf(sumsq / cnt - mean * mean, 0.f);
            const float stdv = fmaxf(sqrtf(var), EPSV);
            s_mean = mean;
            s_rstd = 1.f / stdv;
            s_start = mn;
            s_end   = mx;
        }
    }
    __syncthreads();

    // ---- normalized first 65 values from registers (NaN = invalid mask) ----
    __shared__ float ys[SDIM];
    if (t < 17) {
        const float vals[4] = {v0.x, v0.y, v0.z, v0.w};
        const float mean = s_mean, rstd = s_rstd;
        const int st = s_start, en = s_end;
        #pragma unroll
        for (int e = 0; e < 4; e++) {
            const int idx = 4 * t + e;
            if (idx < SDIM) {
                const bool valid = (idx >= st) && (idx <= en);
                ys[idx] = valid ? (vals[e] - mean) * rstd
                                : __int_as_float(0x7fffffff);
            }
        }
    }
    __syncthreads();

    // ---- phase 1: compute 65x65 matrix into SMEM (conflict-free STS) ----
    // obuf is 16B-aligned and shifted by o = row&3 floats so SMEM index ≡
    // global index (mod 4): aligned LDS.128 pairs with aligned STG.128.
    __shared__ __align__(16) float obuf[OUT_PER_ROW + 8];
    const int o = row & 3;                       // staging shift
    const float ya = ys[lid];                    // conflict-free
    const float yb = ys[lid + 32];               // conflict-free
    const float yc = ys[SDIM - 1];               // broadcast

    #pragma unroll 3
    for (int i = wid; i < SDIM; i += 8) {
        const float yi = ys[i];                  // uniform per warp -> broadcast
        float* __restrict__ oi = obuf + o + i * SDIM;
        oi[lid]      = (fabsf(yi - ya) < THRESH) ? 1.f : 0.f;
        oi[lid + 32] = (fabsf(yi - yb) < THRESH) ? 1.f : 0.f;
        if (lid == 0)
            oi[64]   = (fabsf(yi - yc) < THRESH) ? 1.f : 0.f;
    }
    __syncthreads();

    // ---- phase 2: aligned streaming copy SMEM -> GMEM ----
    float* __restrict__ orow = out + (size_t)row * OUT_PER_ROW;
    const int s = (4 - o) & 3;                   // head scalars (k < s)
    const int m = (OUT_PER_ROW - s) >> 2;        // aligned float4 groups
    const int tail = s + 4 * m;

    if (t == 0)                                   // head (<=3)
        for (int k = 0; k < s; k++) __stcs(&orow[k], obuf[o + k]);
    if (t == 1)                                   // tail (<=3)
        for (int k = tail; k < OUT_PER_ROW; k++) __stcs(&orow[k], obuf[o + k]);

    // body: obuf+o+s is 16B-aligned ((o+s)&3==0, obuf aligned); orow[s+4g] 16B-aligned
    const float4* __restrict__ src = reinterpret_cast<const float4*>(obuf + o + s);
    #pragma unroll 4
    for (int g = t; g < m; g += NTHREADS) {
        __stcs(reinterpret_cast<float4*>(&orow[s + 4 * g]), src[g]);
    }
}

extern "C" void kernel_launch(void* const* d_in, const int* in_sizes, int n_in,
                              void* d_out, int out_size) {
    const float* x = (const float*)d_in[0];
    float* out = (float*)d_out;
    const int nrows = in_sizes[0] / LROW;   // 1024*16 = 16384
    rp_kernel<<<nrows, NTHREADS>>>(x, out);
}